// round 1
// baseline (speedup 1.0000x reference)
#include <cuda_runtime.h>
#include <math.h>

#define BM 128
#define BK 32
#define NMAX 4096

__device__ float  g_sq[NMAX];
__device__ int    g_dom[NMAX];
__device__ double g_sums[2];   // [0]=same, [1]=diff
__device__ double g_den[2];    // [0]=count same, [1]=count diff

// ---------------------------------------------------------------------------
// init: zero accumulators, detect domain dtype (int32 vs int64), decode it,
// and compute the denominators analytically from the domain histogram.
// ---------------------------------------------------------------------------
__global__ void init_kernel(const void* __restrict__ domraw, int N) {
    __shared__ int any_odd;
    __shared__ int cnt[8];
    const int* p = (const int*)domraw;
    int t = threadIdx.x;
    if (t == 0) { any_odd = 0; g_sums[0] = 0.0; g_sums[1] = 0.0; }
    if (t < 8) cnt[t] = 0;
    __syncthreads();

    // If the buffer is int64 (values 0..7), every odd 32-bit word is 0.
    // If it is int32, odd words are random domain values (P(all zero) ~ 8^-2048).
    // Only touch the first N 32-bit words (always in-bounds for either dtype).
    for (int i = t; i < N / 2; i += blockDim.x)
        if (p[2 * i + 1] != 0) any_odd = 1;
    __syncthreads();
    bool is32 = (any_odd != 0);

    for (int i = t; i < N; i += blockDim.x) {
        int v = is32 ? p[i] : p[2 * i];
        g_dom[i] = v;
        atomicAdd(&cnt[v & 7], 1);
    }
    __syncthreads();
    if (t == 0) {
        double cs = 0.0;
        for (int d = 0; d < 8; ++d) cs += (double)cnt[d] * (double)cnt[d];
        g_den[0] = cs;
        g_den[1] = (double)N * (double)N - cs;
    }
}

// ---------------------------------------------------------------------------
// squared row norms: one warp per row
// ---------------------------------------------------------------------------
__global__ void sq_kernel(const float* __restrict__ F, int N, int D) {
    int warp = (blockIdx.x * blockDim.x + threadIdx.x) >> 5;
    int lane = threadIdx.x & 31;
    if (warp >= N) return;
    const float4* row = reinterpret_cast<const float4*>(F + (size_t)warp * D);
    float s = 0.0f;
    int n4 = D >> 2;
    for (int c = lane; c < n4; c += 32) {
        float4 v = row[c];
        s += v.x * v.x + v.y * v.y + v.z * v.z + v.w * v.w;
    }
    #pragma unroll
    for (int o = 16; o > 0; o >>= 1) s += __shfl_xor_sync(0xffffffffu, s, o);
    if (lane == 0) g_sq[warp] = s;
}

// ---------------------------------------------------------------------------
// main: fused tile GEMM (F F^T) + multi-sigma Gaussian kernel epilogue.
// Only tile pairs (ti, tj) with tj >= ti are computed; off-diagonal tiles
// count double (matrix + mask are symmetric).
// ---------------------------------------------------------------------------
__global__ void __launch_bounds__(256, 2)
mmd_main(const float* __restrict__ F, int D, int T)
{
    __shared__ float As[BK][BM];
    __shared__ float Bs[BK][BM];
    __shared__ float sqA[BM], sqB[BM];
    __shared__ int   dAh[BM], dBh[BM];
    __shared__ double red[256];

    // map linear block index -> upper-triangular tile pair
    int rem = blockIdx.x;
    int ti = 0;
    while (rem >= T - ti) { rem -= T - ti; ++ti; }
    int tj = ti + rem;
    int i0 = ti * BM, j0 = tj * BM;

    int tid = threadIdx.x;
    for (int t = tid; t < BM; t += 256) {
        sqA[t] = g_sq[i0 + t]; dAh[t] = g_dom[i0 + t];
        sqB[t] = g_sq[j0 + t]; dBh[t] = g_dom[j0 + t];
    }

    float acc[8][8];
    #pragma unroll
    for (int i = 0; i < 8; ++i)
        #pragma unroll
        for (int j = 0; j < 8; ++j) acc[i][j] = 0.0f;

    int lrow = tid >> 3;   // 0..31
    int lc4  = tid & 7;    // 0..7
    int ty = tid >> 4, tx = tid & 15;

    for (int k0 = 0; k0 < D; k0 += BK) {
        __syncthreads();
        #pragma unroll
        for (int p = 0; p < 4; ++p) {
            int row = lrow + p * 32;
            float4 va = *reinterpret_cast<const float4*>(
                &F[(size_t)(i0 + row) * D + k0 + lc4 * 4]);
            float4 vb = *reinterpret_cast<const float4*>(
                &F[(size_t)(j0 + row) * D + k0 + lc4 * 4]);
            As[lc4 * 4 + 0][row] = va.x; As[lc4 * 4 + 1][row] = va.y;
            As[lc4 * 4 + 2][row] = va.z; As[lc4 * 4 + 3][row] = va.w;
            Bs[lc4 * 4 + 0][row] = vb.x; Bs[lc4 * 4 + 1][row] = vb.y;
            Bs[lc4 * 4 + 2][row] = vb.z; Bs[lc4 * 4 + 3][row] = vb.w;
        }
        __syncthreads();
        #pragma unroll
        for (int k = 0; k < BK; ++k) {
            float a[8], b[8];
            *reinterpret_cast<float4*>(a)     = *reinterpret_cast<float4*>(&As[k][ty * 8]);
            *reinterpret_cast<float4*>(a + 4) = *reinterpret_cast<float4*>(&As[k][ty * 8 + 4]);
            *reinterpret_cast<float4*>(b)     = *reinterpret_cast<float4*>(&Bs[k][tx * 8]);
            *reinterpret_cast<float4*>(b + 4) = *reinterpret_cast<float4*>(&Bs[k][tx * 8 + 4]);
            #pragma unroll
            for (int i = 0; i < 8; ++i)
                #pragma unroll
                for (int j = 0; j < 8; ++j)
                    acc[i][j] = fmaf(a[i], b[j], acc[i][j]);
        }
    }

    // ---- epilogue: d2 -> sum of 12 Gaussian kernels, masked accumulation ----
    // constants are -0.5 * sigma * log2(e); exp2f compiles to MUFU.EX2.
    float s_same = 0.0f, s_diff = 0.0f;
    #pragma unroll
    for (int i = 0; i < 8; ++i) {
        int gi = i0 + ty * 8 + i;
        float sqi = sqA[ty * 8 + i];
        int   di  = dAh[ty * 8 + i];
        #pragma unroll
        for (int j = 0; j < 8; ++j) {
            int gj = j0 + tx * 8 + j;
            float d2 = sqi + sqB[tx * 8 + j] - 2.0f * acc[i][j];
            d2 = (gi == gj) ? 0.0f : fmaxf(d2, 0.0f);
            float kk = exp2f(d2 * -7.2134752e-5f)
                     + exp2f(d2 * -7.2134752e-4f)
                     + exp2f(d2 * -7.2134752e-3f)
                     + exp2f(d2 * -7.2134752e-2f);
            // s >= 1 terms underflow to exactly 0 in fp32 once d2 > ~206.6
            // (the reference's fp32 exp flushes identically) -> skip 8 MUFUs.
            if (d2 < 206.0f) {
                kk += exp2f(d2 * -0.72134752f)
                    + exp2f(d2 * -3.6067376f)
                    + exp2f(d2 * -7.2134752f)
                    + exp2f(d2 * -10.8202128f)
                    + exp2f(d2 * -14.4269504f)
                    + exp2f(d2 * -18.0336880f)
                    + exp2f(d2 * -21.6404256f)
                    + exp2f(d2 * -72.1347520f);
            }
            if (di == dBh[tx * 8 + j]) s_same += kk; else s_diff += kk;
        }
    }
    double w = (ti == tj) ? 1.0 : 2.0;

    // block reduction in fp64, then one atomic per sum per block
    red[tid] = (double)s_same * w;
    __syncthreads();
    #pragma unroll
    for (int o = 128; o > 0; o >>= 1) {
        if (tid < o) red[tid] += red[tid + o];
        __syncthreads();
    }
    if (tid == 0) atomicAdd(&g_sums[0], red[0]);
    __syncthreads();
    red[tid] = (double)s_diff * w;
    __syncthreads();
    #pragma unroll
    for (int o = 128; o > 0; o >>= 1) {
        if (tid < o) red[tid] += red[tid + o];
        __syncthreads();
    }
    if (tid == 0) atomicAdd(&g_sums[1], red[0]);
}

__global__ void final_kernel(float* __restrict__ out) {
    out[0] = (float)(g_sums[0] / g_den[0] - g_sums[1] / g_den[1]);
}

// ---------------------------------------------------------------------------
extern "C" void kernel_launch(void* const* d_in, const int* in_sizes, int n_in,
                              void* d_out, int out_size) {
    const float* F   = (const float*)d_in[0];
    const void*  dom = (const void*)d_in[1];
    int N = in_sizes[1];
    int D = in_sizes[0] / N;
    int T = N / BM;

    init_kernel<<<1, 256>>>(dom, N);
    sq_kernel<<<(N * 32 + 255) / 256, 256>>>(F, N, D);
    mmd_main<<<T * (T + 1) / 2, 256>>>(F, D, T);
    final_kernel<<<1, 1>>>((float*)d_out);
}

// round 3
// speedup vs baseline: 2.1582x; 2.1582x over previous
#include <cuda_runtime.h>
#include <cuda_bf16.h>
#include <stdint.h>
#include <math.h>

#define NMAX 4096
#define DMAX 256
#define BM 128
#define BK 32

__device__ __nv_bfloat16 g_hi[NMAX * DMAX];
__device__ __nv_bfloat16 g_lo[NMAX * DMAX];
__device__ float  g_sq[NMAX];
__device__ int    g_dom[NMAX];
__device__ double g_sums[2];   // [0]=same, [1]=diff
__device__ double g_den[2];

// ---------------- helpers ----------------
__device__ __forceinline__ uint32_t smem_u32(const void* p) {
    uint32_t a;
    asm("{ .reg .u64 t; cvta.to.shared.u64 t, %1; cvt.u32.u64 %0, t; }"
        : "=r"(a) : "l"(p));
    return a;
}
__device__ __forceinline__ void cp16(uint32_t s, const void* g) {
    asm volatile("cp.async.cg.shared.global [%0], [%1], 16;"
                 :: "r"(s), "l"(g) : "memory");
}
__device__ __forceinline__ void cp_commit() {
    asm volatile("cp.async.commit_group;" ::: "memory");
}
template <int N>
__device__ __forceinline__ void cp_wait() {
    asm volatile("cp.async.wait_group %0;" :: "n"(N) : "memory");
}
__device__ __forceinline__ void ldsm_x4(uint32_t* r, uint32_t a) {
    asm volatile("ldmatrix.sync.aligned.m8n8.x4.shared.b16 {%0,%1,%2,%3}, [%4];"
        : "=r"(r[0]), "=r"(r[1]), "=r"(r[2]), "=r"(r[3]) : "r"(a));
}
__device__ __forceinline__ void mma_bf16(float* d, const uint32_t* a,
                                         const uint32_t* b) {
    asm volatile(
        "mma.sync.aligned.m16n8k16.row.col.f32.bf16.bf16.f32 "
        "{%0,%1,%2,%3}, {%4,%5,%6,%7}, {%8,%9}, {%0,%1,%2,%3};"
        : "+f"(d[0]), "+f"(d[1]), "+f"(d[2]), "+f"(d[3])
        : "r"(a[0]), "r"(a[1]), "r"(a[2]), "r"(a[3]), "r"(b[0]), "r"(b[1]));
}

// smem layout (dynamic): two cp.async stages of 4 tiles, each tile 128 rows x 80B
#define ROWB   80
#define TILEB  (128 * ROWB)          // 10240
#define STAGEB (4 * TILEB)           // 40960
#define SM_SQA (2 * STAGEB)          // 81920
#define SM_SQB (SM_SQA + 512)
#define SM_DA  (SM_SQB + 512)
#define SM_DB  (SM_DA + 512)
#define SM_RED (SM_DB + 512)
#define SM_TOTAL (SM_RED + 2048)     // 86016

// ---------------------------------------------------------------------------
// prologue: block 0 decodes domain (int32/int64 autodetect) + denominators;
// other blocks split F rows into bf16 hi/lo and compute fp32 squared norms.
// ---------------------------------------------------------------------------
__global__ void prologue(const float* __restrict__ F,
                         const int* __restrict__ dom, int N, int D) {
    int tid = threadIdx.x;
    if (blockIdx.x == 0) {
        __shared__ int any_odd;
        __shared__ int cnt[8];
        if (tid == 0) { any_odd = 0; g_sums[0] = 0.0; g_sums[1] = 0.0; }
        if (tid < 8) cnt[tid] = 0;
        __syncthreads();
        // int64 values 0..7 -> high words all zero; int32 -> odd words random
        for (int i = tid; i < N / 2; i += blockDim.x)
            if (dom[2 * i + 1] != 0) any_odd = 1;
        __syncthreads();
        bool is32 = (any_odd != 0);
        for (int i = tid; i < N; i += blockDim.x) {
            int v = is32 ? dom[i] : dom[2 * i];
            g_dom[i] = v;
            atomicAdd(&cnt[v & 7], 1);
        }
        __syncthreads();
        if (tid == 0) {
            double cs = 0.0;
            for (int d = 0; d < 8; ++d) cs += (double)cnt[d] * (double)cnt[d];
            g_den[0] = cs;
            g_den[1] = (double)N * (double)N - cs;
        }
        return;
    }
    int warp = tid >> 5, lane = tid & 31;
    int row = (blockIdx.x - 1) * 8 + warp;
    if (row >= N) return;
    const float4* src = reinterpret_cast<const float4*>(F + (size_t)row * D);
    float4 v0 = src[lane * 2], v1 = src[lane * 2 + 1];
    float x[8] = {v0.x, v0.y, v0.z, v0.w, v1.x, v1.y, v1.z, v1.w};
    float s = 0.0f;
    __align__(16) __nv_bfloat16 h8[8];
    __align__(16) __nv_bfloat16 l8[8];
    #pragma unroll
    for (int e = 0; e < 8; ++e) {
        s = fmaf(x[e], x[e], s);
        __nv_bfloat16 h = __float2bfloat16(x[e]);
        h8[e] = h;
        l8[e] = __float2bfloat16(x[e] - __bfloat162float(h));
    }
    *reinterpret_cast<uint4*>(&g_hi[(size_t)row * D + lane * 8]) =
        *reinterpret_cast<const uint4*>(h8);
    *reinterpret_cast<uint4*>(&g_lo[(size_t)row * D + lane * 8]) =
        *reinterpret_cast<const uint4*>(l8);
    #pragma unroll
    for (int o = 16; o > 0; o >>= 1) s += __shfl_xor_sync(0xffffffffu, s, o);
    if (lane == 0) g_sq[row] = s;
}

// ---------------------------------------------------------------------------
// main: HMMA bf16 3-split GEMM (hi*hi + hi*lo + lo*hi) with cp.async double
// buffering + fused multi-sigma Gaussian epilogue. Upper-triangular tiles.
// ---------------------------------------------------------------------------
__global__ void __launch_bounds__(256)
mmd_main(int D, int T) {
    extern __shared__ char sm[];
    uint32_t sb = smem_u32(sm);
    int tid = threadIdx.x, wid = tid >> 5, lane = tid & 31;
    int wm = wid >> 2, wn = wid & 3;           // warp grid 2 x 4

    // linear block -> upper-triangular tile pair
    int rem = blockIdx.x, ti = 0;
    while (rem >= T - ti) { rem -= T - ti; ++ti; }
    int tj = ti + rem;
    int i0 = ti * BM, j0 = tj * BM;

    float* sqA = (float*)(sm + SM_SQA);
    float* sqB = (float*)(sm + SM_SQB);
    int*   dA  = (int*)(sm + SM_DA);
    int*   dB  = (int*)(sm + SM_DB);
    if (tid < 128) {
        sqA[tid] = g_sq[i0 + tid]; dA[tid] = g_dom[i0 + tid];
    } else {
        int t = tid - 128;
        sqB[t] = g_sq[j0 + t]; dB[t] = g_dom[j0 + t];
    }

    const __nv_bfloat16* srcs[4] = {
        g_hi + (size_t)i0 * D, g_lo + (size_t)i0 * D,
        g_hi + (size_t)j0 * D, g_lo + (size_t)j0 * D };

    // per-thread load slot: 8 cp.async of 16B per chunk
    int lrow = tid >> 2;        // 0..63
    int lg   = tid & 3;         // granule 0..3

    auto load_chunk = [&](int kc, int st) {
        uint32_t sdst = sb + st * STAGEB;
        #pragma unroll
        for (int t = 0; t < 4; ++t) {
            const __nv_bfloat16* gsrc = srcs[t] + kc * BK + lg * 8;
            #pragma unroll
            for (int it = 0; it < 2; ++it) {
                int row = lrow + it * 64;
                cp16(sdst + t * TILEB + row * ROWB + lg * 16,
                     gsrc + (size_t)row * D);
            }
        }
    };

    float acc[4][4][4];
    #pragma unroll
    for (int mt = 0; mt < 4; ++mt)
        #pragma unroll
        for (int nt = 0; nt < 4; ++nt)
            #pragma unroll
            for (int e = 0; e < 4; ++e) acc[mt][nt][e] = 0.0f;

    // ldmatrix lane addressing (A: x4 over 16x16; B: x4 over 16(k) x 16(n))
    int a_row = (lane & 15);
    int a_cb  = (lane >> 4) * 16;
    int b_row = ((lane >> 4) & 1) * 8 + (lane & 7);
    int b_cb  = ((lane >> 3) & 1) * 16;

    const int NC = D / BK;   // 8
    load_chunk(0, 0);
    cp_commit();

    for (int kc = 0; kc < NC; ++kc) {
        if (kc + 1 < NC) { load_chunk(kc + 1, (kc + 1) & 1); cp_commit(); }
        if (kc + 1 < NC) cp_wait<1>(); else cp_wait<0>();
        __syncthreads();

        uint32_t stg = sb + (kc & 1) * STAGEB;
        uint32_t aHi = stg + 0 * TILEB + (wm * 64 + a_row) * ROWB + a_cb;
        uint32_t aLo = stg + 1 * TILEB + (wm * 64 + a_row) * ROWB + a_cb;
        uint32_t bHi = stg + 2 * TILEB + (wn * 32 + b_row) * ROWB + b_cb;
        uint32_t bLo = stg + 3 * TILEB + (wn * 32 + b_row) * ROWB + b_cb;

        #pragma unroll
        for (int kf = 0; kf < 2; ++kf) {
            uint32_t ah[4][4], al[4][4], bh[4][2], bl[4][2];
            #pragma unroll
            for (int mt = 0; mt < 4; ++mt) {
                ldsm_x4(ah[mt], aHi + mt * 16 * ROWB + kf * 32);
                ldsm_x4(al[mt], aLo + mt * 16 * ROWB + kf * 32);
            }
            #pragma unroll
            for (int np = 0; np < 2; ++np) {
                uint32_t r[4];
                ldsm_x4(r, bHi + np * 16 * ROWB + kf * 32);
                bh[np * 2][0] = r[0]; bh[np * 2][1] = r[1];
                bh[np * 2 + 1][0] = r[2]; bh[np * 2 + 1][1] = r[3];
                ldsm_x4(r, bLo + np * 16 * ROWB + kf * 32);
                bl[np * 2][0] = r[0]; bl[np * 2][1] = r[1];
                bl[np * 2 + 1][0] = r[2]; bl[np * 2 + 1][1] = r[3];
            }
            #pragma unroll
            for (int mt = 0; mt < 4; ++mt)
                #pragma unroll
                for (int nt = 0; nt < 4; ++nt) {
                    mma_bf16(acc[mt][nt], ah[mt], bh[nt]);
                    mma_bf16(acc[mt][nt], ah[mt], bl[nt]);
                    mma_bf16(acc[mt][nt], al[mt], bh[nt]);
                }
        }
        __syncthreads();
    }

    // ---- epilogue: d2 -> 12-sigma Gaussian sum, masked accumulation ----
    int qr = lane >> 2, qc = lane & 3;
    float s_same = 0.0f, s_diff = 0.0f;
    #pragma unroll
    for (int mt = 0; mt < 4; ++mt) {
        #pragma unroll
        for (int eh = 0; eh < 2; ++eh) {
            int il = wm * 64 + mt * 16 + qr + eh * 8;
            int gi = i0 + il;
            float sqi = sqA[il];
            int   di  = dA[il];
            #pragma unroll
            for (int nt = 0; nt < 4; ++nt) {
                #pragma unroll
                for (int ec = 0; ec < 2; ++ec) {
                    int jl = wn * 32 + nt * 8 + qc * 2 + ec;
                    float a = acc[mt][nt][eh * 2 + ec];
                    float d2 = sqi + sqB[jl] - 2.0f * a;
                    d2 = (gi == (j0 + jl)) ? 0.0f : fmaxf(d2, 0.0f);
                    // constants: -0.5 * sigma * log2(e)
                    float kk = exp2f(d2 * -7.2134752e-5f)
                             + exp2f(d2 * -7.2134752e-4f)
                             + exp2f(d2 * -7.2134752e-3f)
                             + exp2f(d2 * -7.2134752e-2f);
                    if (d2 < 206.0f) {  // s>=1 terms flush to 0 past here
                        kk += exp2f(d2 * -0.72134752f)
                            + exp2f(d2 * -3.6067376f)
                            + exp2f(d2 * -7.2134752f)
                            + exp2f(d2 * -10.8202128f)
                            + exp2f(d2 * -14.4269504f)
                            + exp2f(d2 * -18.0336880f)
                            + exp2f(d2 * -21.6404256f)
                            + exp2f(d2 * -72.1347520f);
                    }
                    if (di == dB[jl]) s_same += kk; else s_diff += kk;
                }
            }
        }
    }

    double w = (ti == tj) ? 1.0 : 2.0;
    double* red = (double*)(sm + SM_RED);
    red[tid] = (double)s_same * w;
    __syncthreads();
    #pragma unroll
    for (int o = 128; o > 0; o >>= 1) {
        if (tid < o) red[tid] += red[tid + o];
        __syncthreads();
    }
    if (tid == 0) atomicAdd(&g_sums[0], red[0]);
    __syncthreads();
    red[tid] = (double)s_diff * w;
    __syncthreads();
    #pragma unroll
    for (int o = 128; o > 0; o >>= 1) {
        if (tid < o) red[tid] += red[tid + o];
        __syncthreads();
    }
    if (tid == 0) atomicAdd(&g_sums[1], red[0]);
}

__global__ void final_kernel(float* __restrict__ out) {
    out[0] = (float)(g_sums[0] / g_den[0] - g_sums[1] / g_den[1]);
}

__global__ void noop_kernel() {}

// ---------------------------------------------------------------------------
extern "C" void kernel_launch(void* const* d_in, const int* in_sizes, int n_in,
                              void* d_out, int out_size) {
    const float* F   = (const float*)d_in[0];
    const int*   dom = (const int*)d_in[1];
    int N = in_sizes[1];
    int D = in_sizes[0] / N;
    int T = N / BM;

    (void)cudaFuncSetAttribute(mmd_main,
        cudaFuncAttributeMaxDynamicSharedMemorySize, SM_TOTAL);

    // exactly 4 launches/iteration so ncu -s 5 lands on mmd_main
    prologue<<<1 + (N + 7) / 8, 256>>>(F, dom, N, D);
    mmd_main<<<T * (T + 1) / 2, 256, SM_TOTAL>>>(D, T);
    final_kernel<<<1, 1>>>((float*)d_out);
    noop_kernel<<<1, 1>>>();
}

// round 4
// speedup vs baseline: 3.1327x; 1.4515x over previous
#include <cuda_runtime.h>
#include <cuda_bf16.h>
#include <stdint.h>
#include <math.h>

#define NMAX 4096
#define DMAX 256
#define BM 128
#define BK 32

__device__ __nv_bfloat16 g_hi[NMAX * DMAX];
__device__ float  g_sq[NMAX];
__device__ int    g_dom[NMAX];
__device__ double g_sums[2];   // [0]=same, [1]=diff
__device__ double g_den[2];

// ---------------- helpers ----------------
__device__ __forceinline__ uint32_t smem_u32(const void* p) {
    uint32_t a;
    asm("{ .reg .u64 t; cvta.to.shared.u64 t, %1; cvt.u32.u64 %0, t; }"
        : "=r"(a) : "l"(p));
    return a;
}
__device__ __forceinline__ void cp16(uint32_t s, const void* g) {
    asm volatile("cp.async.cg.shared.global [%0], [%1], 16;"
                 :: "r"(s), "l"(g) : "memory");
}
__device__ __forceinline__ void cp_commit() {
    asm volatile("cp.async.commit_group;" ::: "memory");
}
template <int N>
__device__ __forceinline__ void cp_wait() {
    asm volatile("cp.async.wait_group %0;" :: "n"(N) : "memory");
}
__device__ __forceinline__ void ldsm_x4(uint32_t* r, uint32_t a) {
    asm volatile("ldmatrix.sync.aligned.m8n8.x4.shared.b16 {%0,%1,%2,%3}, [%4];"
        : "=r"(r[0]), "=r"(r[1]), "=r"(r[2]), "=r"(r[3]) : "r"(a));
}
__device__ __forceinline__ void mma_bf16(float* d, const uint32_t* a,
                                         const uint32_t* b) {
    asm volatile(
        "mma.sync.aligned.m16n8k16.row.col.f32.bf16.bf16.f32 "
        "{%0,%1,%2,%3}, {%4,%5,%6,%7}, {%8,%9}, {%0,%1,%2,%3};"
        : "+f"(d[0]), "+f"(d[1]), "+f"(d[2]), "+f"(d[3])
        : "r"(a[0]), "r"(a[1]), "r"(a[2]), "r"(a[3]), "r"(b[0]), "r"(b[1]));
}

// smem layout: two cp.async stages of 2 bf16 tiles (A,B), 128 rows x 80B
#define ROWB   80
#define TILEB  (128 * ROWB)          // 10240
#define STAGEB (2 * TILEB)           // 20480
#define SM_SQA (2 * STAGEB)          // 40960
#define SM_SQB (SM_SQA + 512)
#define SM_DA  (SM_SQB + 512)
#define SM_DB  (SM_DA + 512)
#define SM_RED (SM_DB + 512)
#define SM_TOTAL (SM_RED + 2048)     // 45056 (44 KB) -> 2 CTAs/SM

// ---------------------------------------------------------------------------
// prologue: block 0 decodes domain (int32/int64 autodetect) + denominators;
// other blocks round F rows to bf16 and compute exact fp32 squared norms.
// ---------------------------------------------------------------------------
__global__ void prologue(const float* __restrict__ F,
                         const int* __restrict__ dom, int N, int D) {
    int tid = threadIdx.x;
    if (blockIdx.x == 0) {
        __shared__ int any_odd;
        __shared__ int cnt[8];
        if (tid == 0) { any_odd = 0; g_sums[0] = 0.0; g_sums[1] = 0.0; }
        if (tid < 8) cnt[tid] = 0;
        __syncthreads();
        // int64 values 0..7 -> high words all zero; int32 -> odd words random
        for (int i = tid; i < N / 2; i += blockDim.x)
            if (dom[2 * i + 1] != 0) any_odd = 1;
        __syncthreads();
        bool is32 = (any_odd != 0);
        for (int i = tid; i < N; i += blockDim.x) {
            int v = is32 ? dom[i] : dom[2 * i];
            g_dom[i] = v;
            atomicAdd(&cnt[v & 7], 1);
        }
        __syncthreads();
        if (tid == 0) {
            double cs = 0.0;
            for (int d = 0; d < 8; ++d) cs += (double)cnt[d] * (double)cnt[d];
            g_den[0] = cs;
            g_den[1] = (double)N * (double)N - cs;
        }
        return;
    }
    int warp = tid >> 5, lane = tid & 31;
    int row = (blockIdx.x - 1) * 8 + warp;
    if (row >= N) return;
    const float4* src = reinterpret_cast<const float4*>(F + (size_t)row * D);
    float4 v0 = src[lane * 2], v1 = src[lane * 2 + 1];
    float x[8] = {v0.x, v0.y, v0.z, v0.w, v1.x, v1.y, v1.z, v1.w};
    float s = 0.0f;
    __align__(16) __nv_bfloat16 h8[8];
    #pragma unroll
    for (int e = 0; e < 8; ++e) {
        s = fmaf(x[e], x[e], s);
        h8[e] = __float2bfloat16(x[e]);
    }
    *reinterpret_cast<uint4*>(&g_hi[(size_t)row * D + lane * 8]) =
        *reinterpret_cast<const uint4*>(h8);
    #pragma unroll
    for (int o = 16; o > 0; o >>= 1) s += __shfl_xor_sync(0xffffffffu, s, o);
    if (lane == 0) g_sq[row] = s;
}

// ---------------------------------------------------------------------------
// main: single-pass HMMA bf16 GEMM with cp.async double buffering + fused
// multi-sigma Gaussian epilogue. Upper-triangular tile pairs, occ 2/SM.
// ---------------------------------------------------------------------------
__global__ void __launch_bounds__(256, 2)
mmd_main(int D, int T) {
    extern __shared__ char sm[];
    uint32_t sb = smem_u32(sm);
    int tid = threadIdx.x, wid = tid >> 5, lane = tid & 31;
    int wm = wid >> 2, wn = wid & 3;           // warp grid 2 x 4

    // linear block -> upper-triangular tile pair
    int rem = blockIdx.x, ti = 0;
    while (rem >= T - ti) { rem -= T - ti; ++ti; }
    int tj = ti + rem;
    int i0 = ti * BM, j0 = tj * BM;

    float* sqA = (float*)(sm + SM_SQA);
    float* sqB = (float*)(sm + SM_SQB);
    int*   dA  = (int*)(sm + SM_DA);
    int*   dB  = (int*)(sm + SM_DB);
    if (tid < 128) {
        sqA[tid] = g_sq[i0 + tid]; dA[tid] = g_dom[i0 + tid];
    } else {
        int t = tid - 128;
        sqB[t] = g_sq[j0 + t]; dB[t] = g_dom[j0 + t];
    }

    const __nv_bfloat16* srcA = g_hi + (size_t)i0 * D;
    const __nv_bfloat16* srcB = g_hi + (size_t)j0 * D;

    // per-thread load slot: 4 cp.async of 16B per chunk
    int lrow = tid >> 2;        // 0..63
    int lg   = tid & 3;         // granule 0..3

    auto load_chunk = [&](int kc, int st) {
        uint32_t sdst = sb + st * STAGEB;
        const __nv_bfloat16* ga = srcA + kc * BK + lg * 8;
        const __nv_bfloat16* gb = srcB + kc * BK + lg * 8;
        #pragma unroll
        for (int it = 0; it < 2; ++it) {
            int row = lrow + it * 64;
            cp16(sdst + row * ROWB + lg * 16, ga + (size_t)row * D);
            cp16(sdst + TILEB + row * ROWB + lg * 16, gb + (size_t)row * D);
        }
    };

    float acc[4][4][4];
    #pragma unroll
    for (int mt = 0; mt < 4; ++mt)
        #pragma unroll
        for (int nt = 0; nt < 4; ++nt)
            #pragma unroll
            for (int e = 0; e < 4; ++e) acc[mt][nt][e] = 0.0f;

    // ldmatrix lane addressing
    int a_row = (lane & 15);
    int a_cb  = (lane >> 4) * 16;
    int b_row = ((lane >> 4) & 1) * 8 + (lane & 7);
    int b_cb  = ((lane >> 3) & 1) * 16;

    const int NC = D / BK;   // 8
    load_chunk(0, 0);
    cp_commit();

    for (int kc = 0; kc < NC; ++kc) {
        if (kc + 1 < NC) { load_chunk(kc + 1, (kc + 1) & 1); cp_commit(); }
        if (kc + 1 < NC) cp_wait<1>(); else cp_wait<0>();
        __syncthreads();

        uint32_t stg = sb + (kc & 1) * STAGEB;
        uint32_t aHi = stg + (wm * 64 + a_row) * ROWB + a_cb;
        uint32_t bHi = stg + TILEB + (wn * 32 + b_row) * ROWB + b_cb;

        #pragma unroll
        for (int kf = 0; kf < 2; ++kf) {
            uint32_t ah[4][4], bh[4][2];
            #pragma unroll
            for (int mt = 0; mt < 4; ++mt)
                ldsm_x4(ah[mt], aHi + mt * 16 * ROWB + kf * 32);
            #pragma unroll
            for (int np = 0; np < 2; ++np) {
                uint32_t r[4];
                ldsm_x4(r, bHi + np * 16 * ROWB + kf * 32);
                bh[np * 2][0] = r[0]; bh[np * 2][1] = r[1];
                bh[np * 2 + 1][0] = r[2]; bh[np * 2 + 1][1] = r[3];
            }
            #pragma unroll
            for (int mt = 0; mt < 4; ++mt)
                #pragma unroll
                for (int nt = 0; nt < 4; ++nt)
                    mma_bf16(acc[mt][nt], ah[mt], bh[nt]);
        }
        __syncthreads();
    }

    // ---- epilogue: d2 -> 12-sigma Gaussian sum, masked accumulation ----
    // 2 MUFUs per pair; the x10-power terms come from 4-FMUL square chains.
    int qr = lane >> 2, qc = lane & 3;
    float s_same = 0.0f, s_diff = 0.0f;
    #pragma unroll
    for (int mt = 0; mt < 4; ++mt) {
        #pragma unroll
        for (int eh = 0; eh < 2; ++eh) {
            int il = wm * 64 + mt * 16 + qr + eh * 8;
            int gi = i0 + il;
            float sqi = sqA[il];
            int   di  = dA[il];
            #pragma unroll
            for (int nt = 0; nt < 4; ++nt) {
                #pragma unroll
                for (int ec = 0; ec < 2; ++ec) {
                    int jl = wn * 32 + nt * 8 + qc * 2 + ec;
                    float a = acc[mt][nt][eh * 2 + ec];
                    float d2 = sqi + sqB[jl] - 2.0f * a;
                    d2 = (gi == (j0 + jl)) ? 0.0f : fmaxf(d2, 0.0f);
                    // tA = exp(-d2/2 * 1e-4); tA^10 = s=1e-3 term
                    float tA = exp2f(d2 * -7.2134752e-5f);
                    float tA2 = tA * tA, tA4 = tA2 * tA2;
                    float eA10 = tA4 * tA4 * tA2;          // tA^10
                    // tB = exp(-d2/2 * 1e-2); tB^10 = s=0.1 term
                    float tB = exp2f(d2 * -7.2134752e-3f);
                    float tB2 = tB * tB, tB4 = tB2 * tB2;
                    float eB10 = tB4 * tB4 * tB2;          // tB^10
                    float kk = tA + eA10 + tB + eB10;
                    if (d2 < 206.0f) {  // s>=1 terms flush to 0 past here
                        kk += exp2f(d2 * -0.72134752f)
                            + exp2f(d2 * -3.6067376f)
                            + exp2f(d2 * -7.2134752f)
                            + exp2f(d2 * -10.8202128f)
                            + exp2f(d2 * -14.4269504f)
                            + exp2f(d2 * -18.0336880f)
                            + exp2f(d2 * -21.6404256f)
                            + exp2f(d2 * -72.1347520f);
                    }
                    if (di == dB[jl]) s_same += kk; else s_diff += kk;
                }
            }
        }
    }

    double w = (ti == tj) ? 1.0 : 2.0;
    double* red = (double*)(sm + SM_RED);
    red[tid] = (double)s_same * w;
    __syncthreads();
    #pragma unroll
    for (int o = 128; o > 0; o >>= 1) {
        if (tid < o) red[tid] += red[tid + o];
        __syncthreads();
    }
    if (tid == 0) atomicAdd(&g_sums[0], red[0]);
    __syncthreads();
    red[tid] = (double)s_diff * w;
    __syncthreads();
    #pragma unroll
    for (int o = 128; o > 0; o >>= 1) {
        if (tid < o) red[tid] += red[tid + o];
        __syncthreads();
    }
    if (tid == 0) atomicAdd(&g_sums[1], red[0]);
}

__global__ void final_kernel(float* __restrict__ out) {
    out[0] = (float)(g_sums[0] / g_den[0] - g_sums[1] / g_den[1]);
}

// ---------------------------------------------------------------------------
extern "C" void kernel_launch(void* const* d_in, const int* in_sizes, int n_in,
                              void* d_out, int out_size) {
    const float* F   = (const float*)d_in[0];
    const int*   dom = (const int*)d_in[1];
    int N = in_sizes[1];
    int D = in_sizes[0] / N;
    int T = N / BM;

    (void)cudaFuncSetAttribute(mmd_main,
        cudaFuncAttributeMaxDynamicSharedMemorySize, SM_TOTAL);

    prologue<<<1 + (N + 7) / 8, 256>>>(F, dom, N, D);
    mmd_main<<<T * (T + 1) / 2, 256, SM_TOTAL>>>(D, T);
    final_kernel<<<1, 1>>>((float*)d_out);
}

// round 5
// speedup vs baseline: 3.3837x; 1.0801x over previous
#include <cuda_runtime.h>
#include <cuda_bf16.h>
#include <stdint.h>
#include <math.h>

#define NMAX 4096
#define DMAX 256
#define BM 128
#define BK 32

__device__ __nv_bfloat16 g_hi[NMAX * DMAX];
__device__ float    g_sq[NMAX];
__device__ int      g_dom[NMAX];
__device__ double   g_sums[2];   // [0]=same, [1]=diff
__device__ double   g_den[2];
__device__ unsigned g_done;

// ---------------- helpers ----------------
__device__ __forceinline__ uint32_t smem_u32(const void* p) {
    uint32_t a;
    asm("{ .reg .u64 t; cvta.to.shared.u64 t, %1; cvt.u32.u64 %0, t; }"
        : "=r"(a) : "l"(p));
    return a;
}
__device__ __forceinline__ void cp16(uint32_t s, const void* g) {
    asm volatile("cp.async.cg.shared.global [%0], [%1], 16;"
                 :: "r"(s), "l"(g) : "memory");
}
__device__ __forceinline__ void cp_commit() {
    asm volatile("cp.async.commit_group;" ::: "memory");
}
template <int N>
__device__ __forceinline__ void cp_wait() {
    asm volatile("cp.async.wait_group %0;" :: "n"(N) : "memory");
}
__device__ __forceinline__ void ldsm_x4(uint32_t* r, uint32_t a) {
    asm volatile("ldmatrix.sync.aligned.m8n8.x4.shared.b16 {%0,%1,%2,%3}, [%4];"
        : "=r"(r[0]), "=r"(r[1]), "=r"(r[2]), "=r"(r[3]) : "r"(a));
}
__device__ __forceinline__ void mma_bf16(float* d, const uint32_t* a,
                                         const uint32_t* b) {
    asm volatile(
        "mma.sync.aligned.m16n8k16.row.col.f32.bf16.bf16.f32 "
        "{%0,%1,%2,%3}, {%4,%5,%6,%7}, {%8,%9}, {%0,%1,%2,%3};"
        : "+f"(d[0]), "+f"(d[1]), "+f"(d[2]), "+f"(d[3])
        : "r"(a[0]), "r"(a[1]), "r"(a[2]), "r"(a[3]), "r"(b[0]), "r"(b[1]));
}

// smem layout: 3 cp.async stages of 2 bf16 tiles (A,B), 128 rows x 80B
#define ROWB   80
#define TILEB  (128 * ROWB)          // 10240
#define STAGEB (2 * TILEB)           // 20480
#define NSTG   3
#define SM_SQA (NSTG * STAGEB)       // 61440
#define SM_SQB (SM_SQA + 512)
#define SM_DA  (SM_SQB + 512)
#define SM_DB  (SM_DA + 512)
#define SM_RED (SM_DB + 512)
#define SM_TOTAL (SM_RED + 256)      // 63744 -> 2 CTAs/SM

// ---------------------------------------------------------------------------
// prologue: block 0 decodes domain (int32/int64 autodetect) + denominators;
// blocks 1..64 round F rows to bf16 and compute exact fp32 squared norms
// (8 rows per warp, unroll 2 for MLP).
// ---------------------------------------------------------------------------
__global__ void prologue(const float* __restrict__ F,
                         const int* __restrict__ dom, int N, int D) {
    int tid = threadIdx.x;
    if (blockIdx.x == 0) {
        __shared__ int any_odd;
        __shared__ int cnt[8];
        if (tid == 0) { any_odd = 0; g_sums[0] = 0.0; g_sums[1] = 0.0; g_done = 0u; }
        if (tid < 8) cnt[tid] = 0;
        __syncthreads();
        // int64 values 0..7 -> high words all zero; int32 -> odd words random
        for (int i = tid; i < N / 2; i += blockDim.x)
            if (dom[2 * i + 1] != 0) any_odd = 1;
        __syncthreads();
        bool is32 = (any_odd != 0);
        for (int i = tid; i < N; i += blockDim.x) {
            int v = is32 ? dom[i] : dom[2 * i];
            g_dom[i] = v;
            atomicAdd(&cnt[v & 7], 1);
        }
        __syncthreads();
        if (tid == 0) {
            double cs = 0.0;
            for (int d = 0; d < 8; ++d) cs += (double)cnt[d] * (double)cnt[d];
            g_den[0] = cs;
            g_den[1] = (double)N * (double)N - cs;
        }
        return;
    }
    int warp = tid >> 5, lane = tid & 31;
    int base = ((blockIdx.x - 1) * 8 + warp) * 8;   // 8 rows per warp
    #pragma unroll 2
    for (int rr = 0; rr < 8; ++rr) {
        int row = base + rr;
        if (row >= N) break;
        const float4* src = reinterpret_cast<const float4*>(F + (size_t)row * D);
        float4 v0 = src[lane * 2], v1 = src[lane * 2 + 1];
        float x[8] = {v0.x, v0.y, v0.z, v0.w, v1.x, v1.y, v1.z, v1.w};
        float s = 0.0f;
        __align__(16) __nv_bfloat16 h8[8];
        #pragma unroll
        for (int e = 0; e < 8; ++e) {
            s = fmaf(x[e], x[e], s);
            h8[e] = __float2bfloat16(x[e]);
        }
        *reinterpret_cast<uint4*>(&g_hi[(size_t)row * D + lane * 8]) =
            *reinterpret_cast<const uint4*>(h8);
        #pragma unroll
        for (int o = 16; o > 0; o >>= 1) s += __shfl_xor_sync(0xffffffffu, s, o);
        if (lane == 0) g_sq[row] = s;
    }
}

// ---------------------------------------------------------------------------
// main: single-pass HMMA bf16 GEMM, 3-stage cp.async ring (1 sync/chunk),
// fused multi-sigma Gaussian epilogue with warp-uniform rare branch,
// shuffle reduction, last-CTA writes the final scalar.
// ---------------------------------------------------------------------------
__global__ void __launch_bounds__(256, 2)
mmd_main(int D, int T, float* __restrict__ out) {
    extern __shared__ char sm[];
    uint32_t sb = smem_u32(sm);
    int tid = threadIdx.x, wid = tid >> 5, lane = tid & 31;
    int wm = wid >> 2, wn = wid & 3;           // warp grid 2 x 4

    // linear block -> upper-triangular tile pair
    int rem = blockIdx.x, ti = 0;
    while (rem >= T - ti) { rem -= T - ti; ++ti; }
    int tj = ti + rem;
    int i0 = ti * BM, j0 = tj * BM;

    float* sqA = (float*)(sm + SM_SQA);
    float* sqB = (float*)(sm + SM_SQB);
    int*   dA  = (int*)(sm + SM_DA);
    int*   dB  = (int*)(sm + SM_DB);
    if (tid < 128) {
        sqA[tid] = g_sq[i0 + tid]; dA[tid] = g_dom[i0 + tid];
    } else {
        int t = tid - 128;
        sqB[t] = g_sq[j0 + t]; dB[t] = g_dom[j0 + t];
    }

    const __nv_bfloat16* srcA = g_hi + (size_t)i0 * D;
    const __nv_bfloat16* srcB = g_hi + (size_t)j0 * D;

    int lrow = tid >> 2;        // 0..63
    int lg   = tid & 3;         // granule 0..3

    auto load_chunk = [&](int kc, int st) {
        uint32_t sdst = sb + st * STAGEB;
        const __nv_bfloat16* ga = srcA + kc * BK + lg * 8;
        const __nv_bfloat16* gb = srcB + kc * BK + lg * 8;
        #pragma unroll
        for (int it = 0; it < 2; ++it) {
            int row = lrow + it * 64;
            cp16(sdst + row * ROWB + lg * 16, ga + (size_t)row * D);
            cp16(sdst + TILEB + row * ROWB + lg * 16, gb + (size_t)row * D);
        }
    };

    float acc[4][4][4];
    #pragma unroll
    for (int mt = 0; mt < 4; ++mt)
        #pragma unroll
        for (int nt = 0; nt < 4; ++nt)
            #pragma unroll
            for (int e = 0; e < 4; ++e) acc[mt][nt][e] = 0.0f;

    // ldmatrix lane addressing
    int a_row = (lane & 15);
    int a_cb  = (lane >> 4) * 16;
    int b_row = ((lane >> 4) & 1) * 8 + (lane & 7);
    int b_cb  = ((lane >> 3) & 1) * 16;

    const int NC = D / BK;   // 8
    load_chunk(0, 0); cp_commit();
    load_chunk(1, 1); cp_commit();

    for (int kc = 0; kc < NC; ++kc) {
        if (kc == NC - 1) cp_wait<0>(); else cp_wait<1>();
        __syncthreads();
        // prefetch kc+2 into the slot consumed at kc-1 (safe: sync passed)
        if (kc + 2 < NC) { load_chunk(kc + 2, (kc + 2) % NSTG); cp_commit(); }

        uint32_t stg = sb + (kc % NSTG) * STAGEB;
        uint32_t aHi = stg + (wm * 64 + a_row) * ROWB + a_cb;
        uint32_t bHi = stg + TILEB + (wn * 32 + b_row) * ROWB + b_cb;

        #pragma unroll
        for (int kf = 0; kf < 2; ++kf) {
            uint32_t ah[4][4], bh[4][2];
            #pragma unroll
            for (int mt = 0; mt < 4; ++mt)
                ldsm_x4(ah[mt], aHi + mt * 16 * ROWB + kf * 32);
            #pragma unroll
            for (int np = 0; np < 2; ++np) {
                uint32_t r[4];
                ldsm_x4(r, bHi + np * 16 * ROWB + kf * 32);
                bh[np * 2][0] = r[0]; bh[np * 2][1] = r[1];
                bh[np * 2 + 1][0] = r[2]; bh[np * 2 + 1][1] = r[3];
            }
            #pragma unroll
            for (int mt = 0; mt < 4; ++mt)
                #pragma unroll
                for (int nt = 0; nt < 4; ++nt)
                    mma_bf16(acc[mt][nt], ah[mt], bh[nt]);
        }
    }

    // ---- epilogue: d2 -> 12-sigma Gaussian sum, masked accumulation ----
    int qr = lane >> 2, qc = lane & 3;
    float s_same = 0.0f, s_diff = 0.0f;
    #pragma unroll
    for (int mt = 0; mt < 4; ++mt) {
        #pragma unroll
        for (int eh = 0; eh < 2; ++eh) {
            int il = wm * 64 + mt * 16 + qr + eh * 8;
            int gi = i0 + il;
            float sqi = sqA[il];
            int   di  = dA[il];
            #pragma unroll
            for (int nt = 0; nt < 4; ++nt) {
                #pragma unroll
                for (int ec = 0; ec < 2; ++ec) {
                    int jl = wn * 32 + nt * 8 + qc * 2 + ec;
                    float a = acc[mt][nt][eh * 2 + ec];
                    float d2 = sqi + sqB[jl] - 2.0f * a;
                    d2 = (gi == (j0 + jl)) ? 0.0f : fmaxf(d2, 0.0f);
                    // tA = exp(-d2/2*1e-4); tA^10 = s=1e-3.  tB likewise for 1e-2/0.1
                    float tA = exp2f(d2 * -7.2134752e-5f);
                    float tA2 = tA * tA, tA4 = tA2 * tA2;
                    float tB = exp2f(d2 * -7.2134752e-3f);
                    float tB2 = tB * tB, tB4 = tB2 * tB2;
                    float kk = tA + tA4 * tA4 * tA2 + tB + tB4 * tB4 * tB2;
                    // s>=1 terms flush to 0 past d2=206; rare -> warp-uniform branch
                    bool need = d2 < 206.0f;
                    if (__any_sync(0xffffffffu, need)) {
                        float ex = exp2f(d2 * -0.72134752f)
                                 + exp2f(d2 * -3.6067376f)
                                 + exp2f(d2 * -7.2134752f)
                                 + exp2f(d2 * -10.8202128f)
                                 + exp2f(d2 * -14.4269504f)
                                 + exp2f(d2 * -18.0336880f)
                                 + exp2f(d2 * -21.6404256f)
                                 + exp2f(d2 * -72.1347520f);
                        if (need) kk += ex;
                    }
                    if (di == dB[jl]) s_same += kk; else s_diff += kk;
                }
            }
        }
    }

    // warp shuffle reduce (fp32), then fp64 across the 8 warps
    #pragma unroll
    for (int o = 16; o > 0; o >>= 1) {
        s_same += __shfl_xor_sync(0xffffffffu, s_same, o);
        s_diff += __shfl_xor_sync(0xffffffffu, s_diff, o);
    }
    double* red = (double*)(sm + SM_RED);
    double w = (ti == tj) ? 1.0 : 2.0;
    if (lane == 0) {
        red[wid]     = (double)s_same * w;
        red[wid + 8] = (double)s_diff * w;
    }
    __syncthreads();
    if (tid == 0) {
        double a = 0.0, b = 0.0;
        #pragma unroll
        for (int k = 0; k < 8; ++k) { a += red[k]; b += red[k + 8]; }
        atomicAdd(&g_sums[0], a);
        atomicAdd(&g_sums[1], b);
        __threadfence();
        unsigned prev = atomicAdd(&g_done, 1u);
        if (prev == gridDim.x - 1) {
            out[0] = (float)(g_sums[0] / g_den[0] - g_sums[1] / g_den[1]);
        }
    }
}

// ---------------------------------------------------------------------------
extern "C" void kernel_launch(void* const* d_in, const int* in_sizes, int n_in,
                              void* d_out, int out_size) {
    const float* F   = (const float*)d_in[0];
    const int*   dom = (const int*)d_in[1];
    int N = in_sizes[1];
    int D = in_sizes[0] / N;
    int T = N / BM;

    (void)cudaFuncSetAttribute(mmd_main,
        cudaFuncAttributeMaxDynamicSharedMemorySize, SM_TOTAL);

    prologue<<<1 + (N + 63) / 64, 256>>>(F, dom, N, D);
    mmd_main<<<T * (T + 1) / 2, 256, SM_TOTAL>>>(D, T, (float*)d_out);
}

// round 6
// speedup vs baseline: 3.7153x; 1.0980x over previous
#include <cuda_runtime.h>
#include <cuda_bf16.h>
#include <stdint.h>
#include <math.h>

#define NMAX 4096
#define DMAX 256
#define BM 128
#define BK 32

__device__ __nv_bfloat16 g_hi[NMAX * DMAX];
__device__ float    g_sq[NMAX];
__device__ int      g_dom[NMAX];
__device__ double   g_sums[2];   // [0]=same, [1]=diff
__device__ double   g_den[2];
__device__ unsigned g_done;

// ---------------- helpers ----------------
__device__ __forceinline__ uint32_t smem_u32(const void* p) {
    uint32_t a;
    asm("{ .reg .u64 t; cvta.to.shared.u64 t, %1; cvt.u32.u64 %0, t; }"
        : "=r"(a) : "l"(p));
    return a;
}
__device__ __forceinline__ void cp16(uint32_t s, const void* g) {
    asm volatile("cp.async.cg.shared.global [%0], [%1], 16;"
                 :: "r"(s), "l"(g) : "memory");
}
__device__ __forceinline__ void cp_commit() {
    asm volatile("cp.async.commit_group;" ::: "memory");
}
template <int N>
__device__ __forceinline__ void cp_wait() {
    asm volatile("cp.async.wait_group %0;" :: "n"(N) : "memory");
}
__device__ __forceinline__ void ldsm_x4(uint32_t* r, uint32_t a) {
    asm volatile("ldmatrix.sync.aligned.m8n8.x4.shared.b16 {%0,%1,%2,%3}, [%4];"
        : "=r"(r[0]), "=r"(r[1]), "=r"(r[2]), "=r"(r[3]) : "r"(a));
}
__device__ __forceinline__ void mma_bf16(float* d, const uint32_t* a,
                                         const uint32_t* b) {
    asm volatile(
        "mma.sync.aligned.m16n8k16.row.col.f32.bf16.bf16.f32 "
        "{%0,%1,%2,%3}, {%4,%5,%6,%7}, {%8,%9}, {%0,%1,%2,%3};"
        : "+f"(d[0]), "+f"(d[1]), "+f"(d[2]), "+f"(d[3])
        : "r"(a[0]), "r"(a[1]), "r"(a[2]), "r"(a[3]), "r"(b[0]), "r"(b[1]));
}

// smem layout: 3 cp.async stages of 2 bf16 tiles (A,B), 128 rows x 80B
#define ROWB   80
#define TILEB  (128 * ROWB)          // 10240
#define STAGEB (2 * TILEB)           // 20480
#define NSTG   3
#define SM_SQA (NSTG * STAGEB)       // 61440
#define SM_SQB (SM_SQA + 512)
#define SM_DA  (SM_SQB + 512)
#define SM_DB  (SM_DA + 512)
#define SM_RED (SM_DB + 512)
#define SM_TOTAL (SM_RED + 512)      // 64000 -> 2 CTAs/SM

// ---------------------------------------------------------------------------
// prologue: block 0 decodes domain (int32/int64 autodetect) + denominators;
// blocks 1.. round F rows to bf16 and compute exact fp32 squared norms.
// ---------------------------------------------------------------------------
__global__ void prologue(const float* __restrict__ F,
                         const int* __restrict__ dom, int N, int D) {
    int tid = threadIdx.x;
    if (blockIdx.x == 0) {
        __shared__ int any_odd;
        __shared__ int cnt[8];
        if (tid == 0) { any_odd = 0; g_sums[0] = 0.0; g_sums[1] = 0.0; g_done = 0u; }
        if (tid < 8) cnt[tid] = 0;
        __syncthreads();
        // int64 values 0..7 -> high words all zero; int32 -> odd words random
        for (int i = tid; i < N / 2; i += blockDim.x)
            if (dom[2 * i + 1] != 0) any_odd = 1;
        __syncthreads();
        bool is32 = (any_odd != 0);
        for (int i = tid; i < N; i += blockDim.x) {
            int v = is32 ? dom[i] : dom[2 * i];
            g_dom[i] = v;
            atomicAdd(&cnt[v & 7], 1);
        }
        __syncthreads();
        if (tid == 0) {
            double cs = 0.0;
            for (int d = 0; d < 8; ++d) cs += (double)cnt[d] * (double)cnt[d];
            g_den[0] = cs;
            g_den[1] = (double)N * (double)N - cs;
        }
        return;
    }
    int warp = tid >> 5, lane = tid & 31;
    int base = ((blockIdx.x - 1) * 8 + warp) * 8;   // 8 rows per warp
    #pragma unroll 2
    for (int rr = 0; rr < 8; ++rr) {
        int row = base + rr;
        if (row >= N) break;
        const float4* src = reinterpret_cast<const float4*>(F + (size_t)row * D);
        float4 v0 = src[lane * 2], v1 = src[lane * 2 + 1];
        float x[8] = {v0.x, v0.y, v0.z, v0.w, v1.x, v1.y, v1.z, v1.w};
        float s = 0.0f;
        __align__(16) __nv_bfloat16 h8[8];
        #pragma unroll
        for (int e = 0; e < 8; ++e) {
            s = fmaf(x[e], x[e], s);
            h8[e] = __float2bfloat16(x[e]);
        }
        *reinterpret_cast<uint4*>(&g_hi[(size_t)row * D + lane * 8]) =
            *reinterpret_cast<const uint4*>(h8);
        #pragma unroll
        for (int o = 16; o > 0; o >>= 1) s += __shfl_xor_sync(0xffffffffu, s, o);
        if (lane == 0) g_sq[row] = s;
    }
}

// ---------------------------------------------------------------------------
// main: single-pass HMMA bf16 GEMM, 512 threads (4x4 warp grid, 32x32 warp
// tiles), 3-stage cp.async ring, fused multi-sigma Gaussian epilogue,
// last-CTA writes the final scalar. 2 CTAs/SM -> 32 warps resident.
// ---------------------------------------------------------------------------
__global__ void __launch_bounds__(512, 2)
mmd_main(int D, int T, float* __restrict__ out) {
    extern __shared__ char sm[];
    uint32_t sb = smem_u32(sm);
    int tid = threadIdx.x, wid = tid >> 5, lane = tid & 31;
    int wm = wid >> 2, wn = wid & 3;           // warp grid 4 x 4

    // linear block -> upper-triangular tile pair
    int rem = blockIdx.x, ti = 0;
    while (rem >= T - ti) { rem -= T - ti; ++ti; }
    int tj = ti + rem;
    int i0 = ti * BM, j0 = tj * BM;

    float* sqA = (float*)(sm + SM_SQA);
    float* sqB = (float*)(sm + SM_SQB);
    int*   dA  = (int*)(sm + SM_DA);
    int*   dB  = (int*)(sm + SM_DB);
    if (tid < 128) {
        sqA[tid] = g_sq[i0 + tid]; dA[tid] = g_dom[i0 + tid];
    } else if (tid < 256) {
        int t = tid - 128;
        sqB[t] = g_sq[j0 + t]; dB[t] = g_dom[j0 + t];
    }

    const __nv_bfloat16* srcA = g_hi + (size_t)i0 * D;
    const __nv_bfloat16* srcB = g_hi + (size_t)j0 * D;

    int lrow = tid >> 2;        // 0..127
    int lg   = tid & 3;         // granule 0..3

    auto load_chunk = [&](int kc, int st) {
        uint32_t sdst = sb + st * STAGEB;
        cp16(sdst + lrow * ROWB + lg * 16,
             srcA + (size_t)lrow * D + kc * BK + lg * 8);
        cp16(sdst + TILEB + lrow * ROWB + lg * 16,
             srcB + (size_t)lrow * D + kc * BK + lg * 8);
    };

    float acc[2][4][4];
    #pragma unroll
    for (int mt = 0; mt < 2; ++mt)
        #pragma unroll
        for (int nt = 0; nt < 4; ++nt)
            #pragma unroll
            for (int e = 0; e < 4; ++e) acc[mt][nt][e] = 0.0f;

    // ldmatrix lane addressing
    int a_row = (lane & 15);
    int a_cb  = (lane >> 4) * 16;
    int b_row = ((lane >> 4) & 1) * 8 + (lane & 7);
    int b_cb  = ((lane >> 3) & 1) * 16;

    const int NC = D / BK;   // 8
    load_chunk(0, 0); cp_commit();
    load_chunk(1, 1); cp_commit();

    for (int kc = 0; kc < NC; ++kc) {
        if (kc == NC - 1) cp_wait<0>(); else cp_wait<1>();
        __syncthreads();
        // prefetch kc+2 into the slot consumed at kc-1 (safe: sync passed)
        if (kc + 2 < NC) { load_chunk(kc + 2, (kc + 2) % NSTG); cp_commit(); }

        uint32_t stg = sb + (kc % NSTG) * STAGEB;
        uint32_t aHi = stg + (wm * 32 + a_row) * ROWB + a_cb;
        uint32_t bHi = stg + TILEB + (wn * 32 + b_row) * ROWB + b_cb;

        #pragma unroll
        for (int kf = 0; kf < 2; ++kf) {
            uint32_t ah[2][4], bh[4][2];
            #pragma unroll
            for (int mt = 0; mt < 2; ++mt)
                ldsm_x4(ah[mt], aHi + mt * 16 * ROWB + kf * 32);
            #pragma unroll
            for (int np = 0; np < 2; ++np) {
                uint32_t r[4];
                ldsm_x4(r, bHi + np * 16 * ROWB + kf * 32);
                bh[np * 2][0] = r[0]; bh[np * 2][1] = r[1];
                bh[np * 2 + 1][0] = r[2]; bh[np * 2 + 1][1] = r[3];
            }
            #pragma unroll
            for (int mt = 0; mt < 2; ++mt)
                #pragma unroll
                for (int nt = 0; nt < 4; ++nt)
                    mma_bf16(acc[mt][nt], ah[mt], bh[nt]);
        }
    }

    // ---- epilogue: d2 -> 12-sigma Gaussian sum, masked accumulation ----
    int qr = lane >> 2, qc = lane & 3;
    float s_same = 0.0f, s_diff = 0.0f;
    #pragma unroll
    for (int mt = 0; mt < 2; ++mt) {
        #pragma unroll
        for (int eh = 0; eh < 2; ++eh) {
            int il = wm * 32 + mt * 16 + qr + eh * 8;
            int gi = i0 + il;
            float sqi = sqA[il];
            int   di  = dA[il];
            #pragma unroll
            for (int nt = 0; nt < 4; ++nt) {
                #pragma unroll
                for (int ec = 0; ec < 2; ++ec) {
                    int jl = wn * 32 + nt * 8 + qc * 2 + ec;
                    float a = acc[mt][nt][eh * 2 + ec];
                    float d2 = sqi + sqB[jl] - 2.0f * a;
                    d2 = (gi == (j0 + jl)) ? 0.0f : fmaxf(d2, 0.0f);
                    // tA = exp(-d2/2*1e-4); tA^10 = s=1e-3.  tB likewise 1e-2/0.1
                    float tA = exp2f(d2 * -7.2134752e-5f);
                    float tA2 = tA * tA, tA4 = tA2 * tA2;
                    float tB = exp2f(d2 * -7.2134752e-3f);
                    float tB2 = tB * tB, tB4 = tB2 * tB2;
                    float kk = tA + tA4 * tA4 * tA2 + tB + tB4 * tB4 * tB2;
                    // s>=1 terms flush to 0 past d2=206; rare -> warp-uniform
                    bool need = d2 < 206.0f;
                    if (__any_sync(0xffffffffu, need)) {
                        float ex = exp2f(d2 * -0.72134752f)
                                 + exp2f(d2 * -3.6067376f)
                                 + exp2f(d2 * -7.2134752f)
                                 + exp2f(d2 * -10.8202128f)
                                 + exp2f(d2 * -14.4269504f)
                                 + exp2f(d2 * -18.0336880f)
                                 + exp2f(d2 * -21.6404256f)
                                 + exp2f(d2 * -72.1347520f);
                        if (need) kk += ex;
                    }
                    if (di == dB[jl]) s_same += kk; else s_diff += kk;
                }
            }
        }
    }

    // warp shuffle reduce (fp32), then fp64 across the 16 warps
    #pragma unroll
    for (int o = 16; o > 0; o >>= 1) {
        s_same += __shfl_xor_sync(0xffffffffu, s_same, o);
        s_diff += __shfl_xor_sync(0xffffffffu, s_diff, o);
    }
    double* red = (double*)(sm + SM_RED);
    double w = (ti == tj) ? 1.0 : 2.0;
    if (lane == 0) {
        red[wid]      = (double)s_same * w;
        red[wid + 16] = (double)s_diff * w;
    }
    __syncthreads();
    if (tid == 0) {
        double a = 0.0, b = 0.0;
        #pragma unroll
        for (int k = 0; k < 16; ++k) { a += red[k]; b += red[k + 16]; }
        atomicAdd(&g_sums[0], a);
        atomicAdd(&g_sums[1], b);
        __threadfence();
        unsigned prev = atomicAdd(&g_done, 1u);
        if (prev == gridDim.x - 1) {
            out[0] = (float)(g_sums[0] / g_den[0] - g_sums[1] / g_den[1]);
        }
    }
}

// ---------------------------------------------------------------------------
extern "C" void kernel_launch(void* const* d_in, const int* in_sizes, int n_in,
                              void* d_out, int out_size) {
    const float* F   = (const float*)d_in[0];
    const int*   dom = (const int*)d_in[1];
    int N = in_sizes[1];
    int D = in_sizes[0] / N;
    int T = N / BM;

    (void)cudaFuncSetAttribute(mmd_main,
        cudaFuncAttributeMaxDynamicSharedMemorySize, SM_TOTAL);

    prologue<<<1 + (N + 63) / 64, 256>>>(F, dom, N, D);
    mmd_main<<<T * (T + 1) / 2, 512, SM_TOTAL>>>(D, T, (float*)d_out);
}